// round 2
// baseline (speedup 1.0000x reference)
#include <cuda_runtime.h>
#include <cuda_bf16.h>
#include <math.h>

// ---------------------------------------------------------------------------
// Problem: Net_67491116089770
//   Decoder: L0 1x1 conv (3->64) on 2x2 + coordconv concat (->66ch)
//            L1..L8: 2x nearest upsample, reflect-pad 1, 3x3 conv, leaky_relu
//            Final: reflect-pad 1, 3x3 conv 16->6, tanh  => flows (3,6,512,512)
//   Blending: flow warp (bilinear, border clamp) of shading + neighbor flows,
//             exp(-sigma*W*dist) weights, normalized sum => (1,3,512,512)
// ---------------------------------------------------------------------------

#define Hh 512
#define Ww 512
#define HW (512*512)

// Ping-pong scratch (max intermediate: 3*16*512*512 floats = 12.58M)
__device__ float g_bufA[3 * 16 * 512 * 512];
__device__ float g_bufB[3 * 16 * 512 * 512];

__device__ __forceinline__ int reflect_idx(int u, int S) {
    u = (u < 0) ? -u : u;
    u = (u >= S) ? (2 * S - 2 - u) : u;
    return u;
}

// ---------------------------------------------------------------------------
// Layer 0: 1x1 conv (3->64) on constant 2x2 upsample of (3,3,1,1) input,
// leaky_relu, then coordconv channels 64 (=2*x) and 65 (=2*y).
// Output: (3,66,2,2)
// ---------------------------------------------------------------------------
__global__ void layer0_kernel(const float* __restrict__ xin,
                              const float* __restrict__ w0,
                              const float* __restrict__ b0,
                              float* __restrict__ out)
{
    int tid = blockIdx.x * blockDim.x + threadIdx.x;
    const int TOTAL = 3 * 66 * 4;
    if (tid >= TOTAL) return;
    int px = tid & 3; int t = tid >> 2;
    int oc = t % 66;  int n = t / 66;
    float v;
    if (oc < 64) {
        v = b0[oc];
        #pragma unroll
        for (int ic = 0; ic < 3; ic++)
            v = fmaf(w0[oc * 3 + ic], xin[n * 3 + ic], v);
        v = (v > 0.f) ? v : 0.01f * v;
    } else {
        int yy = px >> 1, xx = px & 1;
        v = (oc == 64) ? 2.f * (float)xx : 2.f * (float)yy;
    }
    out[(n * 66 + oc) * 4 + px] = v;
}

// ---------------------------------------------------------------------------
// Generic fused layer: (optional 2x nearest upsample) + reflect-pad 1 +
// 3x3 VALID conv + activation (0=leaky_relu 0.01, 1=tanh).
// Each thread: PX consecutive x-pixels x CB output channels in registers.
// ---------------------------------------------------------------------------
template<int IN_CH, int OUT_CH, int CB, int PX, int S_IN, bool UP, int ACT>
__global__ void conv3x3_kernel(const float* __restrict__ in,
                               const float* __restrict__ w,
                               const float* __restrict__ bias,
                               float* __restrict__ out)
{
    constexpr int S_OUT = UP ? 2 * S_IN : S_IN;
    constexpr int NXB = S_OUT / PX;
    constexpr int NOCB = OUT_CH / CB;
    constexpr int TOTAL = 3 * NOCB * S_OUT * NXB;

    int tid = blockIdx.x * blockDim.x + threadIdx.x;
    if (tid >= TOTAL) return;
    int xg = tid % NXB; int t = tid / NXB;
    int oy = t % S_OUT; t /= S_OUT;
    int ocb = t % NOCB; int n = t / NOCB;
    int ox0 = xg * PX;

    float acc[CB][PX];
    #pragma unroll
    for (int j = 0; j < CB; j++) {
        float bv = bias[ocb * CB + j];
        #pragma unroll
        for (int p = 0; p < PX; p++) acc[j][p] = bv;
    }

    const float* inN = in + n * IN_CH * S_IN * S_IN;
    const float* wB  = w + (ocb * CB) * IN_CH * 9;

    #pragma unroll
    for (int ky = 0; ky < 3; ky++) {
        int uy = oy + ky - 1;
        int iy;
        if (UP) { uy = reflect_idx(uy, S_OUT); iy = uy >> 1; }
        else    { iy = reflect_idx(uy, S_IN); }

        int ix[PX + 2];
        #pragma unroll
        for (int t2 = 0; t2 < PX + 2; t2++) {
            int ux = ox0 + t2 - 1;
            if (UP) { ux = reflect_idx(ux, S_OUT); ix[t2] = ux >> 1; }
            else    { ix[t2] = reflect_idx(ux, S_IN); }
        }

        #pragma unroll 1
        for (int ic = 0; ic < IN_CH; ic++) {
            const float* row = inN + (ic * S_IN + iy) * S_IN;
            float v[PX + 2];
            #pragma unroll
            for (int t2 = 0; t2 < PX + 2; t2++) v[t2] = __ldg(row + ix[t2]);
            const float* wr = wB + ic * 9 + ky * 3;
            #pragma unroll
            for (int kx = 0; kx < 3; kx++) {
                #pragma unroll
                for (int j = 0; j < CB; j++) {
                    float wv = __ldg(wr + j * IN_CH * 9 + kx);
                    #pragma unroll
                    for (int p = 0; p < PX; p++)
                        acc[j][p] = fmaf(wv, v[p + kx], acc[j][p]);
                }
            }
        }
    }

    float* outN = out + n * OUT_CH * S_OUT * S_OUT;
    #pragma unroll
    for (int j = 0; j < CB; j++) {
        #pragma unroll
        for (int p = 0; p < PX; p++) {
            float v2 = acc[j][p];
            if (ACT == 0) v2 = (v2 > 0.f) ? v2 : 0.01f * v2;
            else          v2 = tanhf(v2);
            outN[(ocb * CB + j) * S_OUT * S_OUT + oy * S_OUT + ox0 + p] = v2;
        }
    }
}

// ---------------------------------------------------------------------------
// Blending kernel: per output pixel, loop over n in {0,1} neighbors.
// ---------------------------------------------------------------------------
__global__ void blending_kernel(const float* __restrict__ xin,
                                const float* __restrict__ neighbors,
                                const int*   __restrict__ albedo_index,
                                const float* __restrict__ albedos,
                                const float* __restrict__ flows,  // (3,6,512,512)
                                float* __restrict__ out)          // (3,512,512)
{
    int tid = blockIdx.x * blockDim.x + threadIdx.x;
    if (tid >= HW) return;
    int px = tid & 511;
    int py = tid >> 9;

    const float* alb = albedos + albedo_index[0] * 3 * HW;

    float f0[6];
    #pragma unroll
    for (int c = 0; c < 6; c++) f0[c] = flows[c * HW + tid];

    float xs = -1.f + 2.f * (float)px / 511.f;
    float ys = -1.f + 2.f * (float)py / 511.f;

    float alb_c[3];
    #pragma unroll
    for (int c = 0; c < 3; c++) alb_c[c] = alb[c * HW + tid];

    float num[3] = {0.f, 0.f, 0.f};
    float den = 0.f;

    #pragma unroll
    for (int n = 0; n < 2; n++) {
        float dl = xin[0] - xin[(n + 1) * 3 + 0];
        float dv = xin[1] - xin[(n + 1) * 3 + 1];
        float dt = xin[2] - xin[(n + 1) * 3 + 2];
        float flag = (fabsf(dl) > 0.f) ? 1.f : 0.f;

        float ofx = dl * f0[0] + dv * f0[2] + dt * f0[4];
        float ofy = dl * f0[1] + dv * f0[3] + dt * f0[5];

        float gx = xs + ofx, gy = ys + ofy;
        float gpx = fminf(fmaxf((gx + 1.f) * 256.f - 0.5f, 0.f), 511.f);
        float gpy = fminf(fmaxf((gy + 1.f) * 256.f - 0.5f, 0.f), 511.f);
        float x0f = floorf(gpx), y0f = floorf(gpy);
        float wx = gpx - x0f, wy = gpy - y0f;
        int x0i = (int)x0f; x0i = max(0, min(x0i, 511));
        int x1i = min(x0i + 1, 511);
        int y0i = (int)y0f; y0i = max(0, min(y0i, 511));
        int y1i = min(y0i + 1, 511);

        float w00 = (1.f - wx) * (1.f - wy);
        float w01 = wx * (1.f - wy);
        float w10 = (1.f - wx) * wy;
        float w11 = wx * wy;
        int i00 = y0i * 512 + x0i, i01 = y0i * 512 + x1i;
        int i10 = y1i * 512 + x0i, i11 = y1i * 512 + x1i;

        const float* nb = neighbors + n * 3 * HW;
        const float* fn = flows + (n + 1) * 6 * HW;

        float wimg[3];
        #pragma unroll
        for (int c = 0; c < 3; c++) {
            const float* nbc = nb + c * HW;
            const float* ac  = alb + c * HW;
            float s00 = flag * (nbc[i00] / ac[i00]) + (1.f - flag) * nbc[i00];
            float s01 = flag * (nbc[i01] / ac[i01]) + (1.f - flag) * nbc[i01];
            float s10 = flag * (nbc[i10] / ac[i10]) + (1.f - flag) * nbc[i10];
            float s11 = flag * (nbc[i11] / ac[i11]) + (1.f - flag) * nbc[i11];
            float wsv = w00 * s00 + w01 * s01 + w10 * s10 + w11 * s11;
            wimg[c] = flag * wsv * alb_c[c] + (1.f - flag) * wsv;
        }

        float wfv[6];
        #pragma unroll
        for (int c = 0; c < 6; c++) {
            const float* fc = fn + c * HW;
            wfv[c] = w00 * fc[i00] + w01 * fc[i01] + w10 * fc[i10] + w11 * fc[i11];
        }
        float obx = dl * wfv[0] + dv * wfv[2] + dt * wfv[4];
        float oby = dl * wfv[1] + dv * wfv[3] + dt * wfv[5];
        float dist = fabsf(ofx - obx) + fabsf(ofy - oby);
        float wgt = expf(-51.2f * dist);  // SIGMA * W = 0.1 * 512

        #pragma unroll
        for (int c = 0; c < 3; c++) num[c] += wimg[c] * wgt;
        den += wgt;
    }

    float inv = 1.f / (den + 1e-5f);
    #pragma unroll
    for (int c = 0; c < 3; c++) out[c * HW + tid] = num[c] * inv;
}

// ---------------------------------------------------------------------------
// Launch
// Input order (metadata insertion order of setup_inputs):
//   0: x, 1: neighbors, 2: albedo_index,
//   3+2i: w{i}, 4+2i: b{i}  for i in 0..8   (INTERLEAVED, per the setup loop)
//   21: wf, 22: bf, 23: albedos
// ---------------------------------------------------------------------------
extern "C" void kernel_launch(void* const* d_in, const int* in_sizes, int n_in,
                              void* d_out, int out_size)
{
    const float* x          = (const float*)d_in[0];
    const float* neighbors  = (const float*)d_in[1];
    const int*   albedo_idx = (const int*)d_in[2];
    const float* w[9]; const float* b[9];
    for (int i = 0; i < 9; i++) {
        w[i] = (const float*)d_in[3 + 2 * i];
        b[i] = (const float*)d_in[4 + 2 * i];
    }
    const float* wf      = (const float*)d_in[21];
    const float* bf      = (const float*)d_in[22];
    const float* albedos = (const float*)d_in[23];
    float* out = (float*)d_out;

    float *pA = nullptr, *pB = nullptr;
    cudaGetSymbolAddress((void**)&pA, g_bufA);
    cudaGetSymbolAddress((void**)&pB, g_bufB);

    layer0_kernel<<<4, 256>>>(x, w[0], b[0], pA);                      // -> A (3,66,2,2)
    conv3x3_kernel<66, 64, 64, 1,   2, true,  0><<<1,   64 >>>(pA, w[1], b[1], pB); // (3,64,4,4)
    conv3x3_kernel<64, 64, 64, 1,   4, true,  0><<<1,   192>>>(pB, w[2], b[2], pA); // (3,64,8,8)
    conv3x3_kernel<64, 32, 32, 1,   8, true,  0><<<3,   256>>>(pA, w[3], b[3], pB); // (3,32,16,16)
    conv3x3_kernel<32, 32, 32, 2,  16, true,  0><<<6,   256>>>(pB, w[4], b[4], pA); // (3,32,32,32)
    conv3x3_kernel<32, 32, 16, 4,  32, true,  0><<<24,  256>>>(pA, w[5], b[5], pB); // (3,32,64,64)
    conv3x3_kernel<32, 16, 16, 4,  64, true,  0><<<48,  256>>>(pB, w[6], b[6], pA); // (3,16,128,128)
    conv3x3_kernel<16, 16, 16, 4, 128, true,  0><<<192, 256>>>(pA, w[7], b[7], pB); // (3,16,256,256)
    conv3x3_kernel<16, 16, 16, 4, 256, true,  0><<<768, 256>>>(pB, w[8], b[8], pA); // (3,16,512,512)
    conv3x3_kernel<16,  6,  6, 4, 512, false, 1><<<768, 256>>>(pA, wf,  bf,  pB);   // flows (3,6,512,512)

    blending_kernel<<<(HW + 255) / 256, 256>>>(x, neighbors, albedo_idx, albedos, pB, out);
}

// round 3
// speedup vs baseline: 3.2633x; 3.2633x over previous
#include <cuda_runtime.h>
#include <cuda_bf16.h>
#include <math.h>

typedef unsigned long long ull;

#define Hh 512
#define Ww 512
#define HW (512*512)

// Ping-pong scratch (max intermediate: 3*16*512*512 floats = 12.58M)
__device__ float g_bufA[3 * 16 * 512 * 512];
__device__ float g_bufB[3 * 16 * 512 * 512];

__device__ __forceinline__ int reflect_idx(int u, int S) {
    u = (u < 0) ? -u : u;
    u = (u >= S) ? (2 * S - 2 - u) : u;
    return u;
}

// packed f32x2 helpers
__device__ __forceinline__ ull pack2(float lo, float hi) {
    ull r; asm("mov.b64 %0, {%1, %2};" : "=l"(r) : "f"(lo), "f"(hi)); return r;
}
__device__ __forceinline__ void unpack2(float& lo, float& hi, ull v) {
    asm("mov.b64 {%0, %1}, %2;" : "=f"(lo), "=f"(hi) : "l"(v));
}
__device__ __forceinline__ ull fma2(ull a, ull b, ull c) {
    ull d; asm("fma.rn.f32x2 %0, %1, %2, %3;" : "=l"(d) : "l"(a), "l"(b), "l"(c)); return d;
}

// ---------------------------------------------------------------------------
// Layer 0: 1x1 conv (3->64) on 2x2 constant upsample, leaky, + coordconv.
// Output: (3,66,2,2)
// ---------------------------------------------------------------------------
__global__ void layer0_kernel(const float* __restrict__ xin,
                              const float* __restrict__ w0,
                              const float* __restrict__ b0,
                              float* __restrict__ out)
{
    int tid = blockIdx.x * blockDim.x + threadIdx.x;
    const int TOTAL = 3 * 66 * 4;
    if (tid >= TOTAL) return;
    int px = tid & 3; int t = tid >> 2;
    int oc = t % 66;  int n = t / 66;
    float v;
    if (oc < 64) {
        v = b0[oc];
        #pragma unroll
        for (int ic = 0; ic < 3; ic++)
            v = fmaf(w0[oc * 3 + ic], xin[n * 3 + ic], v);
        v = (v > 0.f) ? v : 0.01f * v;
    } else {
        int yy = px >> 1, xx = px & 1;
        v = (oc == 64) ? 2.f * (float)xx : 2.f * (float)yy;
    }
    out[(n * 66 + oc) * 4 + px] = v;
}

// ---------------------------------------------------------------------------
// Small layers (L1..L4): block = (n, oc-group). Full input + weight slice in
// shared memory. Threads cover (oc_local, pixel). Upsample+reflect+3x3+leaky.
// ---------------------------------------------------------------------------
template<int IN_CH, int OUT_CH, int S_IN, int OCB>
__global__ void conv_small(const float* __restrict__ in,
                           const float* __restrict__ w,
                           const float* __restrict__ bias,
                           float* __restrict__ out)
{
    constexpr int S_OUT = 2 * S_IN;
    constexpr int PIX = S_OUT * S_OUT;
    constexpr int NOG = OUT_CH / OCB;

    __shared__ float inp[IN_CH * S_IN * S_IN];
    __shared__ float wsm[OCB * IN_CH * 9];
    __shared__ float bsm[OCB];

    int tid = threadIdx.x;
    int n  = blockIdx.x / NOG;
    int og = blockIdx.x % NOG;

    const float* inN = in + n * IN_CH * S_IN * S_IN;
    for (int i = tid; i < IN_CH * S_IN * S_IN; i += 256) inp[i] = inN[i];
    const float* wG = w + og * OCB * IN_CH * 9;
    for (int i = tid; i < OCB * IN_CH * 9; i += 256) wsm[i] = wG[i];
    if (tid < OCB) bsm[tid] = bias[og * OCB + tid];
    __syncthreads();

    for (int idx = tid; idx < OCB * PIX; idx += 256) {
        int oc_l = idx / PIX;
        int pix  = idx % PIX;
        int oy = pix / S_OUT, ox = pix % S_OUT;

        int iy[3], ix[3];
        #pragma unroll
        for (int k = 0; k < 3; k++) {
            iy[k] = reflect_idx(oy + k - 1, S_OUT) >> 1;
            ix[k] = reflect_idx(ox + k - 1, S_OUT) >> 1;
        }

        float a0 = bsm[oc_l], a1 = 0.f, a2 = 0.f;
        const float* wp = wsm + oc_l * IN_CH * 9;
        #pragma unroll 1
        for (int ic = 0; ic < IN_CH; ic++) {
            const float* ib = inp + ic * S_IN * S_IN;
            const float* wr = wp + ic * 9;
            float r0 = ib[iy[0] * S_IN + ix[0]], r1 = ib[iy[0] * S_IN + ix[1]], r2 = ib[iy[0] * S_IN + ix[2]];
            a0 = fmaf(wr[0], r0, a0); a0 = fmaf(wr[1], r1, a0); a0 = fmaf(wr[2], r2, a0);
            float s0 = ib[iy[1] * S_IN + ix[0]], s1 = ib[iy[1] * S_IN + ix[1]], s2 = ib[iy[1] * S_IN + ix[2]];
            a1 = fmaf(wr[3], s0, a1); a1 = fmaf(wr[4], s1, a1); a1 = fmaf(wr[5], s2, a1);
            float t0 = ib[iy[2] * S_IN + ix[0]], t1 = ib[iy[2] * S_IN + ix[1]], t2 = ib[iy[2] * S_IN + ix[2]];
            a2 = fmaf(wr[6], t0, a2); a2 = fmaf(wr[7], t1, a2); a2 = fmaf(wr[8], t2, a2);
        }
        float v = a0 + a1 + a2;
        v = (v > 0.f) ? v : 0.01f * v;
        out[((n * OUT_CH + og * OCB + oc_l) * S_OUT + oy) * S_OUT + ox] = v;
    }
}

// ---------------------------------------------------------------------------
// Big layers (L5..L8, final): block owns one (n, ocb) slice. Weights staged
// in smem pre-duplicated as (w,w) pairs; math via packed fma.rn.f32x2.
// Each thread: PX consecutive x-pixels x CB output channels.
// ACT: 0=leaky_relu(0.01), 1=tanh.
// ---------------------------------------------------------------------------
template<int IN_CH, int OUT_CH, int CB, int PX, int S_IN, bool UP, int ACT>
__global__ void conv_big(const float* __restrict__ in,
                         const float* __restrict__ w,
                         const float* __restrict__ bias,
                         float* __restrict__ out)
{
    constexpr int S_OUT = UP ? 2 * S_IN : S_IN;
    constexpr int NXB = S_OUT / PX;
    constexpr int NOCB = OUT_CH / CB;
    constexpr int NP2 = PX / 2;

    __shared__ ull wsm[CB * IN_CH * 9];
    __shared__ float bsm[CB];

    int tid = threadIdx.x;
    int n   = blockIdx.y / NOCB;
    int ocb = blockIdx.y % NOCB;

    const float* wG = w + (ocb * CB) * IN_CH * 9;
    for (int i = tid; i < CB * IN_CH * 9; i += 256) {
        float wv = wG[i];
        wsm[i] = pack2(wv, wv);
    }
    if (tid < CB) bsm[tid] = bias[ocb * CB + tid];
    __syncthreads();

    int t = blockIdx.x * 256 + tid;
    if (t >= S_OUT * NXB) return;
    int oy = t / NXB;
    int ox0 = (t % NXB) * PX;

    int iy[3];
    #pragma unroll
    for (int k = 0; k < 3; k++) {
        int uy = oy + k - 1;
        if (UP) iy[k] = reflect_idx(uy, S_OUT) >> 1;
        else    iy[k] = reflect_idx(uy, S_IN);
    }
    int ix[PX + 2];
    #pragma unroll
    for (int t2 = 0; t2 < PX + 2; t2++) {
        int ux = ox0 + t2 - 1;
        if (UP) ix[t2] = reflect_idx(ux, S_OUT) >> 1;
        else    ix[t2] = reflect_idx(ux, S_IN);
    }

    ull acc2[CB][NP2];
    #pragma unroll
    for (int cb = 0; cb < CB; cb++) {
        float bv = bsm[cb];
        ull pb = pack2(bv, bv);
        #pragma unroll
        for (int j = 0; j < NP2; j++) acc2[cb][j] = pb;
    }

    const float* inN = in + n * IN_CH * S_IN * S_IN;

    #pragma unroll
    for (int ky = 0; ky < 3; ky++) {
        #pragma unroll 1
        for (int ic = 0; ic < IN_CH; ic++) {
            const float* row = inN + (ic * S_IN + iy[ky]) * S_IN;
            float v[PX + 2];
            #pragma unroll
            for (int t2 = 0; t2 < PX + 2; t2++) v[t2] = __ldg(row + ix[t2]);
            #pragma unroll
            for (int kx = 0; kx < 3; kx++) {
                ull p[NP2];
                #pragma unroll
                for (int j = 0; j < NP2; j++) p[j] = pack2(v[2 * j + kx], v[2 * j + 1 + kx]);
                #pragma unroll
                for (int cb = 0; cb < CB; cb++) {
                    ull wv = wsm[(cb * IN_CH + ic) * 9 + ky * 3 + kx];
                    #pragma unroll
                    for (int j = 0; j < NP2; j++)
                        acc2[cb][j] = fma2(wv, p[j], acc2[cb][j]);
                }
            }
        }
    }

    float* outN = out + ((n * OUT_CH + ocb * CB) * S_OUT + oy) * S_OUT + ox0;
    #pragma unroll
    for (int cb = 0; cb < CB; cb++) {
        #pragma unroll
        for (int j = 0; j < NP2; j++) {
            float lo, hi;
            unpack2(lo, hi, acc2[cb][j]);
            if (ACT == 0) {
                lo = (lo > 0.f) ? lo : 0.01f * lo;
                hi = (hi > 0.f) ? hi : 0.01f * hi;
            } else {
                lo = tanhf(lo); hi = tanhf(hi);
            }
            float2 st; st.x = lo; st.y = hi;
            *reinterpret_cast<float2*>(outN + cb * S_OUT * S_OUT + 2 * j) = st;
        }
    }
}

// ---------------------------------------------------------------------------
// Blending kernel
// ---------------------------------------------------------------------------
__global__ void blending_kernel(const float* __restrict__ xin,
                                const float* __restrict__ neighbors,
                                const int*   __restrict__ albedo_index,
                                const float* __restrict__ albedos,
                                const float* __restrict__ flows,  // (3,6,512,512)
                                float* __restrict__ out)          // (3,512,512)
{
    int tid = blockIdx.x * blockDim.x + threadIdx.x;
    if (tid >= HW) return;
    int px = tid & 511;
    int py = tid >> 9;

    const float* alb = albedos + albedo_index[0] * 3 * HW;

    float f0[6];
    #pragma unroll
    for (int c = 0; c < 6; c++) f0[c] = flows[c * HW + tid];

    float xs = -1.f + 2.f * (float)px / 511.f;
    float ys = -1.f + 2.f * (float)py / 511.f;

    float alb_c[3];
    #pragma unroll
    for (int c = 0; c < 3; c++) alb_c[c] = alb[c * HW + tid];

    float num[3] = {0.f, 0.f, 0.f};
    float den = 0.f;

    #pragma unroll
    for (int n = 0; n < 2; n++) {
        float dl = xin[0] - xin[(n + 1) * 3 + 0];
        float dv = xin[1] - xin[(n + 1) * 3 + 1];
        float dt = xin[2] - xin[(n + 1) * 3 + 2];
        float flag = (fabsf(dl) > 0.f) ? 1.f : 0.f;

        float ofx = dl * f0[0] + dv * f0[2] + dt * f0[4];
        float ofy = dl * f0[1] + dv * f0[3] + dt * f0[5];

        float gx = xs + ofx, gy = ys + ofy;
        float gpx = fminf(fmaxf((gx + 1.f) * 256.f - 0.5f, 0.f), 511.f);
        float gpy = fminf(fmaxf((gy + 1.f) * 256.f - 0.5f, 0.f), 511.f);
        float x0f = floorf(gpx), y0f = floorf(gpy);
        float wx = gpx - x0f, wy = gpy - y0f;
        int x0i = (int)x0f; x0i = max(0, min(x0i, 511));
        int x1i = min(x0i + 1, 511);
        int y0i = (int)y0f; y0i = max(0, min(y0i, 511));
        int y1i = min(y0i + 1, 511);

        float w00 = (1.f - wx) * (1.f - wy);
        float w01 = wx * (1.f - wy);
        float w10 = (1.f - wx) * wy;
        float w11 = wx * wy;
        int i00 = y0i * 512 + x0i, i01 = y0i * 512 + x1i;
        int i10 = y1i * 512 + x0i, i11 = y1i * 512 + x1i;

        const float* nb = neighbors + n * 3 * HW;
        const float* fn = flows + (n + 1) * 6 * HW;

        float wimg[3];
        #pragma unroll
        for (int c = 0; c < 3; c++) {
            const float* nbc = nb + c * HW;
            const float* ac  = alb + c * HW;
            float s00 = flag * (nbc[i00] / ac[i00]) + (1.f - flag) * nbc[i00];
            float s01 = flag * (nbc[i01] / ac[i01]) + (1.f - flag) * nbc[i01];
            float s10 = flag * (nbc[i10] / ac[i10]) + (1.f - flag) * nbc[i10];
            float s11 = flag * (nbc[i11] / ac[i11]) + (1.f - flag) * nbc[i11];
            float wsv = w00 * s00 + w01 * s01 + w10 * s10 + w11 * s11;
            wimg[c] = flag * wsv * alb_c[c] + (1.f - flag) * wsv;
        }

        float wfv[6];
        #pragma unroll
        for (int c = 0; c < 6; c++) {
            const float* fc = fn + c * HW;
            wfv[c] = w00 * fc[i00] + w01 * fc[i01] + w10 * fc[i10] + w11 * fc[i11];
        }
        float obx = dl * wfv[0] + dv * wfv[2] + dt * wfv[4];
        float oby = dl * wfv[1] + dv * wfv[3] + dt * wfv[5];
        float dist = fabsf(ofx - obx) + fabsf(ofy - oby);
        float wgt = expf(-51.2f * dist);  // SIGMA * W = 0.1 * 512

        #pragma unroll
        for (int c = 0; c < 3; c++) num[c] += wimg[c] * wgt;
        den += wgt;
    }

    float inv = 1.f / (den + 1e-5f);
    #pragma unroll
    for (int c = 0; c < 3; c++) out[c * HW + tid] = num[c] * inv;
}

// ---------------------------------------------------------------------------
// Launch
// Input order: 0:x, 1:neighbors, 2:albedo_index,
//              3+2i: w{i}, 4+2i: b{i} (interleaved), 21:wf, 22:bf, 23:albedos
// ---------------------------------------------------------------------------
extern "C" void kernel_launch(void* const* d_in, const int* in_sizes, int n_in,
                              void* d_out, int out_size)
{
    const float* x          = (const float*)d_in[0];
    const float* neighbors  = (const float*)d_in[1];
    const int*   albedo_idx = (const int*)d_in[2];
    const float* w[9]; const float* b[9];
    for (int i = 0; i < 9; i++) {
        w[i] = (const float*)d_in[3 + 2 * i];
        b[i] = (const float*)d_in[4 + 2 * i];
    }
    const float* wf      = (const float*)d_in[21];
    const float* bf      = (const float*)d_in[22];
    const float* albedos = (const float*)d_in[23];
    float* out = (float*)d_out;

    float *pA = nullptr, *pB = nullptr;
    cudaGetSymbolAddress((void**)&pA, g_bufA);
    cudaGetSymbolAddress((void**)&pB, g_bufB);

    layer0_kernel<<<4, 256>>>(x, w[0], b[0], pA);                 // A (3,66,2,2)

    conv_small<66, 64, 2, 16><<<12, 256>>>(pA, w[1], b[1], pB);   // B (3,64,4,4)
    conv_small<64, 64, 4,  4><<<48, 256>>>(pB, w[2], b[2], pA);   // A (3,64,8,8)
    conv_small<64, 32, 8,  1><<<96, 256>>>(pA, w[3], b[3], pB);   // B (3,32,16,16)
    conv_small<32, 32, 16, 1><<<96, 256>>>(pB, w[4], b[4], pA);   // A (3,32,32,32)

    // big layers: grid = (spatial_threads/256, 3*NOCB)
    conv_big<32, 32, 8, 8,  32, true,  0><<<dim3(  2, 12), 256>>>(pA, w[5], b[5], pB); // (3,32,64,64)
    conv_big<32, 16, 8, 8,  64, true,  0><<<dim3(  8,  6), 256>>>(pB, w[6], b[6], pA); // (3,16,128,128)
    conv_big<16, 16, 8, 8, 128, true,  0><<<dim3( 32,  6), 256>>>(pA, w[7], b[7], pB); // (3,16,256,256)
    conv_big<16, 16, 8, 8, 256, true,  0><<<dim3(128,  6), 256>>>(pB, w[8], b[8], pA); // (3,16,512,512)
    conv_big<16,  6, 6, 8, 512, false, 1><<<dim3(128,  3), 256>>>(pA, wf,  bf,  pB);   // flows (3,6,512,512)

    blending_kernel<<<(HW + 255) / 256, 256>>>(x, neighbors, albedo_idx, albedos, pB, out);
}

// round 4
// speedup vs baseline: 4.6995x; 1.4401x over previous
#include <cuda_runtime.h>
#include <cuda_bf16.h>
#include <math.h>

typedef unsigned long long ull;

#define HW (512*512)

__device__ float g_bufA[3 * 16 * 512 * 512];
__device__ float g_bufB[3 * 16 * 512 * 512];

__device__ __forceinline__ int reflect_idx(int u, int S) {
    u = (u < 0) ? -u : u;
    u = (u >= S) ? (2 * S - 2 - u) : u;
    return u;
}

__device__ __forceinline__ ull pack2(float lo, float hi) {
    ull r; asm("mov.b64 %0, {%1, %2};" : "=l"(r) : "f"(lo), "f"(hi)); return r;
}
__device__ __forceinline__ void unpack2(float& lo, float& hi, ull v) {
    asm("mov.b64 {%0, %1}, %2;" : "=f"(lo), "=f"(hi) : "l"(v));
}
__device__ __forceinline__ ull fma2(ull a, ull b, ull c) {
    ull d; asm("fma.rn.f32x2 %0, %1, %2, %3;" : "=l"(d) : "l"(a), "l"(b), "l"(c)); return d;
}

// ---------------------------------------------------------------------------
// Layer 0: 1x1 conv (3->64) on 2x2 constant upsample, leaky, + coordconv.
// ---------------------------------------------------------------------------
__global__ void layer0_kernel(const float* __restrict__ xin,
                              const float* __restrict__ w0,
                              const float* __restrict__ b0,
                              float* __restrict__ out)
{
    int tid = blockIdx.x * blockDim.x + threadIdx.x;
    const int TOTAL = 3 * 66 * 4;
    if (tid >= TOTAL) return;
    int px = tid & 3; int t = tid >> 2;
    int oc = t % 66;  int n = t / 66;
    float v;
    if (oc < 64) {
        v = b0[oc];
        #pragma unroll
        for (int ic = 0; ic < 3; ic++)
            v = fmaf(w0[oc * 3 + ic], xin[n * 3 + ic], v);
        v = (v > 0.f) ? v : 0.01f * v;
    } else {
        int yy = px >> 1, xx = px & 1;
        v = (oc == 64) ? 2.f * (float)xx : 2.f * (float)yy;
    }
    out[(n * 66 + oc) * 4 + px] = v;
}

// ---------------------------------------------------------------------------
// Small layers (L1..L4): block = (n, oc-group, pixel-split). Input + weights
// in smem. PSPLIT multiplies block count to cover more SMs.
// ---------------------------------------------------------------------------
template<int IN_CH, int OUT_CH, int S_IN, int OCB, int PSPLIT>
__global__ void conv_small(const float* __restrict__ in,
                           const float* __restrict__ w,
                           const float* __restrict__ bias,
                           float* __restrict__ out)
{
    constexpr int S_OUT = 2 * S_IN;
    constexpr int PIX = S_OUT * S_OUT;
    constexpr int PPIX = PIX / PSPLIT;
    constexpr int NOG = OUT_CH / OCB;

    __shared__ float inp[IN_CH * S_IN * S_IN];
    __shared__ float wsm[OCB * IN_CH * 9];
    __shared__ float bsm[OCB];

    int tid = threadIdx.x;
    int bt = blockDim.x;
    int b = blockIdx.x;
    int ps = b % PSPLIT; b /= PSPLIT;
    int og = b % NOG;    int n = b / NOG;

    const float* inN = in + n * IN_CH * S_IN * S_IN;
    for (int i = tid; i < IN_CH * S_IN * S_IN; i += bt) inp[i] = inN[i];
    const float* wG = w + og * OCB * IN_CH * 9;
    for (int i = tid; i < OCB * IN_CH * 9; i += bt) wsm[i] = wG[i];
    if (tid < OCB) bsm[tid] = bias[og * OCB + tid];
    __syncthreads();

    for (int idx = tid; idx < OCB * PPIX; idx += bt) {
        int oc_l = idx / PPIX;
        int pix  = ps * PPIX + idx % PPIX;
        int oy = pix / S_OUT, ox = pix % S_OUT;

        int iy[3], ix[3];
        #pragma unroll
        for (int k = 0; k < 3; k++) {
            iy[k] = reflect_idx(oy + k - 1, S_OUT) >> 1;
            ix[k] = reflect_idx(ox + k - 1, S_OUT) >> 1;
        }

        float a0 = bsm[oc_l], a1 = 0.f, a2 = 0.f;
        const float* wp = wsm + oc_l * IN_CH * 9;
        #pragma unroll 2
        for (int ic = 0; ic < IN_CH; ic++) {
            const float* ib = inp + ic * S_IN * S_IN;
            const float* wr = wp + ic * 9;
            float r0 = ib[iy[0] * S_IN + ix[0]], r1 = ib[iy[0] * S_IN + ix[1]], r2 = ib[iy[0] * S_IN + ix[2]];
            a0 = fmaf(wr[0], r0, a0); a0 = fmaf(wr[1], r1, a0); a0 = fmaf(wr[2], r2, a0);
            float s0 = ib[iy[1] * S_IN + ix[0]], s1 = ib[iy[1] * S_IN + ix[1]], s2 = ib[iy[1] * S_IN + ix[2]];
            a1 = fmaf(wr[3], s0, a1); a1 = fmaf(wr[4], s1, a1); a1 = fmaf(wr[5], s2, a1);
            float t0 = ib[iy[2] * S_IN + ix[0]], t1 = ib[iy[2] * S_IN + ix[1]], t2 = ib[iy[2] * S_IN + ix[2]];
            a2 = fmaf(wr[6], t0, a2); a2 = fmaf(wr[7], t1, a2); a2 = fmaf(wr[8], t2, a2);
        }
        float v = a0 + a1 + a2;
        v = (v > 0.f) ? v : 0.01f * v;
        out[((n * OUT_CH + og * OCB + oc_l) * S_OUT + oy) * S_OUT + ox] = v;
    }
}

// ---------------------------------------------------------------------------
// Upsampling big layers (L5..L8): exploit 2x-upsample row/col duplication.
// For each output row, only TWO distinct input rows are needed; the doubled
// ky taps get their weights pre-summed in smem per row-parity.
// Per thread: 8 output px (4 f32x2 lanes) x CB channels. Input loaded as
// one aligned float4 + 2 edge scalars per (row, ic).
// ---------------------------------------------------------------------------
template<int IN_CH, int OUT_CH, int CB, int S_IN>
__global__ void conv_big_up(const float* __restrict__ in,
                            const float* __restrict__ w,
                            const float* __restrict__ bias,
                            float* __restrict__ out)
{
    constexpr int S_OUT = 2 * S_IN;
    constexpr int NXB = S_OUT / 8;
    constexpr int NOCB = OUT_CH / CB;
    constexpr int WN = 12 * CB * IN_CH;  // [p][row][kx][cb][ic]

    __shared__ ull wsm[WN];
    __shared__ float bsm[CB];

    int tid = threadIdx.x;
    int bt = blockDim.x;
    int n   = blockIdx.y / NOCB;
    int ocb = blockIdx.y % NOCB;

    const float* wG = w + (ocb * CB) * IN_CH * 9;
    for (int i = tid; i < WN; i += bt) {
        int ic = i % IN_CH; int r = i / IN_CH;
        int cb = r % CB; r /= CB;
        int kx = r % 3;  r /= 3;
        int row = r % 2; int p = r / 2;
        const float* wb = wG + (cb * IN_CH + ic) * 9 + kx;
        float w0 = wb[0], w1 = wb[3], w2 = wb[6];
        float wv = (p == 0) ? (row == 0 ? w0 : w1 + w2)
                            : (row == 0 ? w0 + w1 : w2);
        wsm[i] = pack2(wv, wv);
    }
    if (tid < CB) bsm[tid] = bias[ocb * CB + tid];
    __syncthreads();

    int t = blockIdx.x * bt + tid;
    if (t >= S_OUT * NXB) return;
    int oy  = t / NXB;
    int ox0 = (t % NXB) * 8;
    int m   = ox0 >> 1;
    int p   = oy & 1;

    int iyA = reflect_idx(oy - 1, S_OUT) >> 1;
    int iyB = reflect_idx(oy + 1, S_OUT) >> 1;

    ull acc[CB][4];
    #pragma unroll
    for (int cb = 0; cb < CB; cb++) {
        float bv = bsm[cb];
        ull pb = pack2(bv, bv);
        #pragma unroll
        for (int j = 0; j < 4; j++) acc[cb][j] = pb;
    }

    const float* inN = in + n * IN_CH * S_IN * S_IN;
    const ull* wP = wsm + p * 2 * 3 * CB * IN_CH;

    #pragma unroll 1
    for (int ic = 0; ic < IN_CH; ic++) {
        const float* rowA = inN + (ic * S_IN + iyA) * S_IN;
        const float* rowB = inN + (ic * S_IN + iyB) * S_IN;

        #pragma unroll
        for (int rr = 0; rr < 2; rr++) {
            const float* row = rr ? rowB : rowA;
            float4 q = *reinterpret_cast<const float4*>(row + m);
            float d0 = (m > 0) ? __ldg(row + m - 1) : q.x;
            float d5 = (m + 4 < S_IN) ? __ldg(row + m + 4) : q.w;
            // sliding pairs s_j = (d_j, d_{j+1}), splats t_j = (d_j, d_j)
            ull s0 = pack2(d0, q.x), s1 = pack2(q.x, q.y), s2 = pack2(q.y, q.z);
            ull s3 = pack2(q.z, q.w), s4 = pack2(q.w, d5);
            ull t1 = pack2(q.x, q.x), t2 = pack2(q.y, q.y);
            ull t3 = pack2(q.z, q.z), t4 = pack2(q.w, q.w);

            const ull* wR = wP + rr * 3 * CB * IN_CH + ic;
            #pragma unroll
            for (int cb = 0; cb < CB; cb++) {
                ull w0 = wR[(0 * CB + cb) * IN_CH];
                ull w1 = wR[(1 * CB + cb) * IN_CH];
                ull w2 = wR[(2 * CB + cb) * IN_CH];
                acc[cb][0] = fma2(w0, s0, acc[cb][0]);
                acc[cb][0] = fma2(w1, t1, acc[cb][0]);
                acc[cb][0] = fma2(w2, s1, acc[cb][0]);
                acc[cb][1] = fma2(w0, s1, acc[cb][1]);
                acc[cb][1] = fma2(w1, t2, acc[cb][1]);
                acc[cb][1] = fma2(w2, s2, acc[cb][1]);
                acc[cb][2] = fma2(w0, s2, acc[cb][2]);
                acc[cb][2] = fma2(w1, t3, acc[cb][2]);
                acc[cb][2] = fma2(w2, s3, acc[cb][2]);
                acc[cb][3] = fma2(w0, s3, acc[cb][3]);
                acc[cb][3] = fma2(w1, t4, acc[cb][3]);
                acc[cb][3] = fma2(w2, s4, acc[cb][3]);
            }
        }
    }

    float* outN = out + ((n * OUT_CH + ocb * CB) * S_OUT + oy) * S_OUT + ox0;
    #pragma unroll
    for (int cb = 0; cb < CB; cb++) {
        #pragma unroll
        for (int j = 0; j < 4; j++) {
            float lo, hi;
            unpack2(lo, hi, acc[cb][j]);
            lo = (lo > 0.f) ? lo : 0.01f * lo;
            hi = (hi > 0.f) ? hi : 0.01f * hi;
            float2 st; st.x = lo; st.y = hi;
            *reinterpret_cast<float2*>(outN + cb * S_OUT * S_OUT + 2 * j) = st;
        }
    }
}

// ---------------------------------------------------------------------------
// Final layer: reflect-pad 1 + 3x3 conv 16->6 + tanh, 512x512, no upsample.
// ---------------------------------------------------------------------------
template<int IN_CH, int OUT_CH>
__global__ void conv_final(const float* __restrict__ in,
                           const float* __restrict__ w,
                           const float* __restrict__ bias,
                           float* __restrict__ out)
{
    constexpr int S = 512;
    constexpr int NXB = S / 8;
    constexpr int WN = OUT_CH * IN_CH * 9;

    __shared__ ull wsm[WN];
    __shared__ float bsm[OUT_CH];

    int tid = threadIdx.x;
    int bt = blockDim.x;
    int n = blockIdx.y;

    for (int i = tid; i < WN; i += bt) { float wv = w[i]; wsm[i] = pack2(wv, wv); }
    if (tid < OUT_CH) bsm[tid] = bias[tid];
    __syncthreads();

    int t = blockIdx.x * bt + tid;
    if (t >= S * NXB) return;
    int oy  = t / NXB;
    int ox0 = (t % NXB) * 8;

    int iy[3];
    #pragma unroll
    for (int k = 0; k < 3; k++) iy[k] = reflect_idx(oy + k - 1, S);

    ull acc[OUT_CH][4];
    #pragma unroll
    for (int cb = 0; cb < OUT_CH; cb++) {
        float bv = bsm[cb];
        ull pb = pack2(bv, bv);
        #pragma unroll
        for (int j = 0; j < 4; j++) acc[cb][j] = pb;
    }

    const float* inN = in + n * IN_CH * S * S;

    #pragma unroll 1
    for (int ic = 0; ic < IN_CH; ic++) {
        #pragma unroll
        for (int ky = 0; ky < 3; ky++) {
            const float* row = inN + (ic * S + iy[ky]) * S;
            float4 qa = *reinterpret_cast<const float4*>(row + ox0);
            float4 qb = *reinterpret_cast<const float4*>(row + ox0 + 4);
            float d0 = (ox0 > 0) ? __ldg(row + ox0 - 1) : __ldg(row + 1);
            float d9 = (ox0 + 8 < S) ? __ldg(row + ox0 + 8) : __ldg(row + S - 2);
            // v indices: d0=v0 .. d9=v9 ; e_j=(v2j,v2j+1), o_j=(v2j+1,v2j+2)
            ull e0 = pack2(d0, qa.x),  e1 = pack2(qa.y, qa.z);
            ull e2 = pack2(qa.w, qb.x), e3 = pack2(qb.y, qb.z);
            ull e4 = pack2(qb.w, d9);
            ull o0 = pack2(qa.x, qa.y), o1 = pack2(qa.z, qa.w);
            ull o2 = pack2(qb.x, qb.y), o3 = pack2(qb.z, qb.w);
            ull ee[5] = {e0, e1, e2, e3, e4};
            ull oo[4] = {o0, o1, o2, o3};

            const ull* wR = wsm + ic * 9 + ky * 3;
            #pragma unroll
            for (int cb = 0; cb < OUT_CH; cb++) {
                ull w0 = wR[cb * IN_CH * 9 + 0];
                ull w1 = wR[cb * IN_CH * 9 + 1];
                ull w2 = wR[cb * IN_CH * 9 + 2];
                #pragma unroll
                for (int j = 0; j < 4; j++) {
                    acc[cb][j] = fma2(w0, ee[j], acc[cb][j]);
                    acc[cb][j] = fma2(w1, oo[j], acc[cb][j]);
                    acc[cb][j] = fma2(w2, ee[j + 1], acc[cb][j]);
                }
            }
        }
    }

    float* outN = out + ((n * OUT_CH) * S + oy) * S + ox0;
    #pragma unroll
    for (int cb = 0; cb < OUT_CH; cb++) {
        #pragma unroll
        for (int j = 0; j < 4; j++) {
            float lo, hi;
            unpack2(lo, hi, acc[cb][j]);
            lo = tanhf(lo); hi = tanhf(hi);
            float2 st; st.x = lo; st.y = hi;
            *reinterpret_cast<float2*>(outN + cb * S * S + 2 * j) = st;
        }
    }
}

// ---------------------------------------------------------------------------
// Blending kernel
// ---------------------------------------------------------------------------
__global__ void blending_kernel(const float* __restrict__ xin,
                                const float* __restrict__ neighbors,
                                const int*   __restrict__ albedo_index,
                                const float* __restrict__ albedos,
                                const float* __restrict__ flows,
                                float* __restrict__ out)
{
    int tid = blockIdx.x * blockDim.x + threadIdx.x;
    if (tid >= HW) return;
    int px = tid & 511;
    int py = tid >> 9;

    const float* alb = albedos + albedo_index[0] * 3 * HW;

    float f0[6];
    #pragma unroll
    for (int c = 0; c < 6; c++) f0[c] = flows[c * HW + tid];

    float xs = -1.f + 2.f * (float)px / 511.f;
    float ys = -1.f + 2.f * (float)py / 511.f;

    float alb_c[3];
    #pragma unroll
    for (int c = 0; c < 3; c++) alb_c[c] = alb[c * HW + tid];

    float num[3] = {0.f, 0.f, 0.f};
    float den = 0.f;

    #pragma unroll
    for (int n = 0; n < 2; n++) {
        float dl = xin[0] - xin[(n + 1) * 3 + 0];
        float dv = xin[1] - xin[(n + 1) * 3 + 1];
        float dt = xin[2] - xin[(n + 1) * 3 + 2];
        float flag = (fabsf(dl) > 0.f) ? 1.f : 0.f;

        float ofx = dl * f0[0] + dv * f0[2] + dt * f0[4];
        float ofy = dl * f0[1] + dv * f0[3] + dt * f0[5];

        float gx = xs + ofx, gy = ys + ofy;
        float gpx = fminf(fmaxf((gx + 1.f) * 256.f - 0.5f, 0.f), 511.f);
        float gpy = fminf(fmaxf((gy + 1.f) * 256.f - 0.5f, 0.f), 511.f);
        float x0f = floorf(gpx), y0f = floorf(gpy);
        float wx = gpx - x0f, wy = gpy - y0f;
        int x0i = (int)x0f; x0i = max(0, min(x0i, 511));
        int x1i = min(x0i + 1, 511);
        int y0i = (int)y0f; y0i = max(0, min(y0i, 511));
        int y1i = min(y0i + 1, 511);

        float w00 = (1.f - wx) * (1.f - wy);
        float w01 = wx * (1.f - wy);
        float w10 = (1.f - wx) * wy;
        float w11 = wx * wy;
        int i00 = y0i * 512 + x0i, i01 = y0i * 512 + x1i;
        int i10 = y1i * 512 + x0i, i11 = y1i * 512 + x1i;

        const float* nb = neighbors + n * 3 * HW;
        const float* fn = flows + (n + 1) * 6 * HW;

        float wimg[3];
        #pragma unroll
        for (int c = 0; c < 3; c++) {
            const float* nbc = nb + c * HW;
            const float* ac  = alb + c * HW;
            float s00 = flag * (nbc[i00] / ac[i00]) + (1.f - flag) * nbc[i00];
            float s01 = flag * (nbc[i01] / ac[i01]) + (1.f - flag) * nbc[i01];
            float s10 = flag * (nbc[i10] / ac[i10]) + (1.f - flag) * nbc[i10];
            float s11 = flag * (nbc[i11] / ac[i11]) + (1.f - flag) * nbc[i11];
            float wsv = w00 * s00 + w01 * s01 + w10 * s10 + w11 * s11;
            wimg[c] = flag * wsv * alb_c[c] + (1.f - flag) * wsv;
        }

        float wfv[6];
        #pragma unroll
        for (int c = 0; c < 6; c++) {
            const float* fc = fn + c * HW;
            wfv[c] = w00 * fc[i00] + w01 * fc[i01] + w10 * fc[i10] + w11 * fc[i11];
        }
        float obx = dl * wfv[0] + dv * wfv[2] + dt * wfv[4];
        float oby = dl * wfv[1] + dv * wfv[3] + dt * wfv[5];
        float dist = fabsf(ofx - obx) + fabsf(ofy - oby);
        float wgt = expf(-51.2f * dist);

        #pragma unroll
        for (int c = 0; c < 3; c++) num[c] += wimg[c] * wgt;
        den += wgt;
    }

    float inv = 1.f / (den + 1e-5f);
    #pragma unroll
    for (int c = 0; c < 3; c++) out[c * HW + tid] = num[c] * inv;
}

// ---------------------------------------------------------------------------
// Launch. Inputs: 0:x 1:neighbors 2:albedo_index, 3+2i:w{i} 4+2i:b{i},
//                 21:wf 22:bf 23:albedos
// ---------------------------------------------------------------------------
extern "C" void kernel_launch(void* const* d_in, const int* in_sizes, int n_in,
                              void* d_out, int out_size)
{
    const float* x          = (const float*)d_in[0];
    const float* neighbors  = (const float*)d_in[1];
    const int*   albedo_idx = (const int*)d_in[2];
    const float* w[9]; const float* b[9];
    for (int i = 0; i < 9; i++) {
        w[i] = (const float*)d_in[3 + 2 * i];
        b[i] = (const float*)d_in[4 + 2 * i];
    }
    const float* wf      = (const float*)d_in[21];
    const float* bf      = (const float*)d_in[22];
    const float* albedos = (const float*)d_in[23];
    float* out = (float*)d_out;

    float *pA = nullptr, *pB = nullptr;
    cudaGetSymbolAddress((void**)&pA, g_bufA);
    cudaGetSymbolAddress((void**)&pB, g_bufB);

    layer0_kernel<<<4, 256>>>(x, w[0], b[0], pA);                     // A (3,66,2,2)

    conv_small<66, 64, 2, 16, 1><<< 12, 256>>>(pA, w[1], b[1], pB);   // B (3,64,4,4)
    conv_small<64, 64, 4,  4, 2><<< 96, 128>>>(pB, w[2], b[2], pA);   // A (3,64,8,8)
    conv_small<64, 32, 8,  1, 2><<<192, 128>>>(pA, w[3], b[3], pB);   // B (3,32,16,16)
    conv_small<32, 32, 16, 1, 4><<<384, 256>>>(pB, w[4], b[4], pA);   // A (3,32,32,32)

    conv_big_up<32, 32, 4,  32><<<dim3(  4, 24), 128>>>(pA, w[5], b[5], pB); // (3,32,64,64)
    conv_big_up<32, 16, 4,  64><<<dim3(  8, 12), 256>>>(pB, w[6], b[6], pA); // (3,16,128,128)
    conv_big_up<16, 16, 8, 128><<<dim3( 32,  6), 256>>>(pA, w[7], b[7], pB); // (3,16,256,256)
    conv_big_up<16, 16, 8, 256><<<dim3(128,  6), 256>>>(pB, w[8], b[8], pA); // (3,16,512,512)
    conv_final<16, 6><<<dim3(128, 3), 256>>>(pA, wf, bf, pB);                // flows (3,6,512,512)

    blending_kernel<<<(HW + 255) / 256, 256>>>(x, neighbors, albedo_idx, albedos, pB, out);
}